// round 17
// baseline (speedup 1.0000x reference)
#include <cuda_runtime.h>
#include <cuda_fp16.h>
#include <cstdint>
#include <cstddef>

// ============================================================================
// NF4Linear: out[8192,4096] = x[8192,4096] @ W^T[4096,4096]
//   W = dequant_nf4(indices, q_scales) -> fp16 (bit-exact vs reference cast)
//   x fp32 -> fp16 (only error source, ~2e-4 rel)
// GEMM core = R10 config (tensor 74.3%, 611us): mma.sync m16n8k16, 128x128
// CTA tile, BK=64, 3-stage cp.async, 256 thr = 8 warps (4m x 2n, 32x64),
// 2 CTAs/SM.
// R14->R15: PERSISTENT CTAs (grid 304) + atomic tile stealing. The cp.async
// pipeline stays warm across tile boundaries (prefetch of next tile's first
// chunks issues during current tile's last iters; epilogue overlaps loads).
// ncu showed tensor=74.3% / L1=60.6% / DRAM=4.4%: stalls, not bandwidth.
// This removes ~6 cold prologues + epilogue bubbles per SM slot.
// ============================================================================

#define OUT_F 4096
#define IN_F  4096
#define M_TOTAL 8192

#define BM 128
#define BN 128
#define BK 64
#define K_TILES (IN_F / BK)      // 64
#define N_TILES_TOT 2048         // (4096/128) * (8192/128)
#define GRID_P 304               // 2 CTAs/SM x 152 SMs (stealing absorbs 148)
#define STAGES 3
#define A_BYTES (BM * 128)       // 16384
#define B_BYTES (BN * 128)       // 16384
#define STAGE_BYTES (A_BYTES + B_BYTES)       // 32768
#define SMEM_DYN (STAGES * STAGE_BYTES + 32)  // + tile-steal slots
#define NTHREADS 256

// Prep kernel grid split
#define DQ_BLOCKS 8192           // 8192*256 threads * 8 weights = 16M weights
#define CV_BLOCKS 16384          // 16384*256 threads * 8 floats  = 32M elems

// Scratch in device globals (allocation-guard-safe per skill rules)
__device__ __half g_W[(size_t)OUT_F * IN_F];     // 32 MB
__device__ __half g_X[(size_t)M_TOTAL * IN_F];   // 64 MB
__device__ int g_ctr;                            // persistent tile counter

__constant__ float c_nf4[16] = {
    -1.0f, -0.6961928009986877f, -0.5250730514526367f, -0.39491748809814453f,
    -0.28444138169288635f, -0.18477343022823334f, -0.09105003625154495f, 0.0f,
    0.07958029955625534f, 0.16093020141124725f, 0.24611230194568634f,
    0.33791524171829224f, 0.44070982933044434f, 0.5626170039176941f,
    0.7229568362236023f, 1.0f};

// ---------------------------------------------------------------------------
// Helpers (arch-generic PTX only)
// ---------------------------------------------------------------------------
__device__ __forceinline__ uint32_t smem_u32(const void* p) {
    uint32_t a;
    asm("{ .reg .u64 t; cvta.to.shared.u64 t, %1; cvt.u32.u64 %0, t; }"
        : "=r"(a) : "l"(p));
    return a;
}

__device__ __forceinline__ void cp16(uint32_t s, const void* g) {
    asm volatile("cp.async.cg.shared.global [%0], [%1], 16;" :: "r"(s), "l"(g));
}

__device__ __forceinline__ void ldsm4(uint32_t* r, uint32_t addr) {
    asm volatile("ldmatrix.sync.aligned.m8n8.x4.shared.b16 {%0,%1,%2,%3}, [%4];"
                 : "=r"(r[0]), "=r"(r[1]), "=r"(r[2]), "=r"(r[3]) : "r"(addr));
}

__device__ __forceinline__ void mma16816(float* c, const uint32_t* a,
                                         const uint32_t* b) {
    asm volatile(
        "mma.sync.aligned.m16n8k16.row.col.f32.f16.f16.f32 "
        "{%0,%1,%2,%3}, {%4,%5,%6,%7}, {%8,%9}, {%0,%1,%2,%3};"
        : "+f"(c[0]), "+f"(c[1]), "+f"(c[2]), "+f"(c[3])
        : "r"(a[0]), "r"(a[1]), "r"(a[2]), "r"(a[3]), "r"(b[0]), "r"(b[1]));
}

// SW128-style swizzle for 128B rows: XOR 16B-col bits with (row&7)
__device__ __forceinline__ uint32_t swz(int row, int col16) {
    return (uint32_t)(row * 128) + (((uint32_t)col16 * 16) ^ ((uint32_t)(row & 7) << 4));
}

// ---------------------------------------------------------------------------
// Fused prep: blocks [0, DQ_BLOCKS) dequantize W; the rest convert x.
// Block 0 thread 0 also resets the persistent-GEMM tile counter (prep is
// ordered before gemm in-stream, every graph replay).
// ---------------------------------------------------------------------------
__global__ __launch_bounds__(256) void prep_kernel(
    const int* __restrict__ idx, const int* __restrict__ qs,
    const float* __restrict__ x) {
    if (blockIdx.x == 0 && threadIdx.x == 0) g_ctr = 0;

    if (blockIdx.x < DQ_BLOCKS) {
        __shared__ float lut[16];
        if (threadIdx.x < 16) lut[threadIdx.x] = c_nf4[threadIdx.x];
        __syncthreads();

        size_t t = (size_t)blockIdx.x * 256 + threadIdx.x;  // 8 weights/thread
        float absmax = ((float)qs[t >> 3] / 127.0f) * 0.05f;  // ref op order

        const int4* ip = reinterpret_cast<const int4*>(idx) + t * 2;
        int4 a = ip[0];
        int4 b = ip[1];
        __half h[8];
        h[0] = __float2half_rn(lut[a.x] * absmax);
        h[1] = __float2half_rn(lut[a.y] * absmax);
        h[2] = __float2half_rn(lut[a.z] * absmax);
        h[3] = __float2half_rn(lut[a.w] * absmax);
        h[4] = __float2half_rn(lut[b.x] * absmax);
        h[5] = __float2half_rn(lut[b.y] * absmax);
        h[6] = __float2half_rn(lut[b.z] * absmax);
        h[7] = __float2half_rn(lut[b.w] * absmax);
        reinterpret_cast<uint4*>(g_W)[t] = *reinterpret_cast<uint4*>(h);
    } else {
        size_t t = (size_t)(blockIdx.x - DQ_BLOCKS) * 256 + threadIdx.x;
        const float4* xp = reinterpret_cast<const float4*>(x) + t * 2;
        float4 a = xp[0];
        float4 b = xp[1];
        __half h[8];
        h[0] = __float2half_rn(a.x); h[1] = __float2half_rn(a.y);
        h[2] = __float2half_rn(a.z); h[3] = __float2half_rn(a.w);
        h[4] = __float2half_rn(b.x); h[5] = __float2half_rn(b.y);
        h[6] = __float2half_rn(b.z); h[7] = __float2half_rn(b.w);
        reinterpret_cast<uint4*>(g_X)[t] = *reinterpret_cast<uint4*>(h);
    }
}

// ---------------------------------------------------------------------------
// Persistent GEMM: D[M,N] = A[M,K].B[N,K]^T  (A=g_X, B=g_W, K-major fp16)
// 304 CTAs steal tiles (tile id: tn = id & 31, tm = id >> 5). The 3-stage
// cp.async ring runs continuously across tiles.
// ---------------------------------------------------------------------------
__device__ __forceinline__ void load_stage(uint32_t sA, const __half* a0,
                                           const __half* b0, int tid) {
    const uint32_t sBb = sA + A_BYTES;
    #pragma unroll
    for (int i = tid; i < BM * 8; i += NTHREADS) {     // 4 iters
        const int r = i >> 3, c = i & 7;
        cp16(sA + swz(r, c), a0 + (size_t)r * IN_F + c * 8);
    }
    #pragma unroll
    for (int i = tid; i < BN * 8; i += NTHREADS) {     // 4 iters
        const int r = i >> 3, c = i & 7;
        cp16(sBb + swz(r, c), b0 + (size_t)r * IN_F + c * 8);
    }
}

__device__ __forceinline__ void chunk_ptrs(int tile, int kt,
                                           const __half*& a0,
                                           const __half*& b0) {
    const int tm = tile >> 5;
    const int tn = tile & 31;
    a0 = g_X + ((size_t)tm * BM) * IN_F + kt * BK;
    b0 = g_W + ((size_t)tn * BN) * IN_F + kt * BK;
}

__global__ __launch_bounds__(NTHREADS, 2)
void gemm_kernel(float* __restrict__ out) {
    extern __shared__ __align__(1024) char smem[];
    const uint32_t sb = smem_u32(smem);
    // tile-steal slots live after the 3 stages
    int* s_tiles = reinterpret_cast<int*>(smem + STAGES * STAGE_BYTES);

    const int tid = threadIdx.x;
    const int lane = tid & 31;
    const int wid = tid >> 5;
    const int mw = wid >> 1;   // 0..3  (m position of warp, 32 rows each)
    const int nw = wid & 1;    // 0..1  (n position of warp, 64 cols each)

    // ldmatrix lane decomposition
    const int t4 = lane >> 3;
    const int i8 = lane & 7;
    const int rowA0 = mw * 32 + ((t4 & 1) << 3) + i8;
    const int rowB0 = nw * 64 + ((t4 >> 1) << 3) + i8;
    const int acolsel = t4 >> 1;
    const int bcolsel = t4 & 1;

    // ---- steal first two tiles ----
    if (tid == 0) {
        s_tiles[0] = atomicAdd(&g_ctr, 1);
        s_tiles[1] = atomicAdd(&g_ctr, 1);
    }
    __syncthreads();
    int t_cur = s_tiles[0];
    int t_nxt = s_tiles[1];
    if (t_cur >= N_TILES_TOT) return;   // uniform across block

    // ---- prologue: chunks (t_cur,0), (t_cur,1) ----
    #pragma unroll
    for (int s = 0; s < STAGES - 1; ++s) {
        const __half *a0, *b0;
        chunk_ptrs(t_cur, s, a0, b0);
        load_stage(sb + s * STAGE_BYTES, a0, b0, tid);
        asm volatile("cp.async.commit_group;" ::: "memory");
    }

    int s_cur = 0;   // buffer holding the chunk being computed
    int s_nxt = 2;   // buffer receiving the prefetch (2 ahead)

    while (t_cur < N_TILES_TOT) {
        float acc[2][8][4];
        #pragma unroll
        for (int mi = 0; mi < 2; ++mi)
            #pragma unroll
            for (int o = 0; o < 8; ++o)
                #pragma unroll
                for (int q = 0; q < 4; ++q) acc[mi][o][q] = 0.0f;

        int t_steal = N_TILES_TOT;   // the tile after t_nxt, stolen mid-tile

        for (int kt = 0; kt < K_TILES; ++kt) {
            asm volatile("cp.async.wait_group 1;" ::: "memory");
            __syncthreads();

            // steal the tile-after-next once per tile (pipelined one tile out)
            if (kt == 0 && tid == 0)
                s_tiles[0] = atomicAdd(&g_ctr, 1);

            // prefetch chunk kt+2 (may belong to the next tile)
            {
                int pk = kt + 2;
                int pt = t_cur;
                if (pk >= K_TILES) { pt = t_nxt; pk -= K_TILES; }
                if (pt < N_TILES_TOT) {
                    const __half *a0, *b0;
                    chunk_ptrs(pt, pk, a0, b0);
                    load_stage(sb + s_nxt * STAGE_BYTES, a0, b0, tid);
                }
            }
            asm volatile("cp.async.commit_group;" ::: "memory");

            const uint32_t sA = sb + s_cur * STAGE_BYTES;
            const uint32_t sBb = sA + A_BYTES;

            #pragma unroll
            for (int ks = 0; ks < BK / 16; ++ks) {
                uint32_t a[2][4], b[4][4];
                ldsm4(a[0], sA + swz(rowA0, 2 * ks + acolsel));
                ldsm4(a[1], sA + swz(rowA0 + 16, 2 * ks + acolsel));
                #pragma unroll
                for (int p = 0; p < 4; ++p)
                    ldsm4(b[p], sBb + swz(rowB0 + p * 16, 2 * ks + bcolsel));
                #pragma unroll
                for (int mi = 0; mi < 2; ++mi)
                    #pragma unroll
                    for (int p = 0; p < 4; ++p) {
                        mma16816(acc[mi][2 * p + 0], a[mi], &b[p][0]);
                        mma16816(acc[mi][2 * p + 1], a[mi], &b[p][2]);
                    }
            }

            // read the stolen tile id late (barrier-separated from the write)
            if (kt == K_TILES - 1) t_steal = s_tiles[0];

            s_cur = (s_cur == 2) ? 0 : s_cur + 1;
            s_nxt = (s_nxt == 2) ? 0 : s_nxt + 1;
        }

        // ---- epilogue for t_cur (next tile's loads already in flight) ----
        {
            const int tm = t_cur >> 5;
            const int tn = t_cur & 31;
            const int gid = lane >> 2;
            const int tq = lane & 3;
            #pragma unroll
            for (int mi = 0; mi < 2; ++mi) {
                const size_t r0 = (size_t)(tm * BM + mw * 32 + mi * 16 + gid);
                #pragma unroll
                for (int oct = 0; oct < 8; ++oct) {
                    const size_t n = (size_t)(tn * BN + nw * 64 + oct * 8 + 2 * tq);
                    float2 v0 = make_float2(acc[mi][oct][0], acc[mi][oct][1]);
                    float2 v1 = make_float2(acc[mi][oct][2], acc[mi][oct][3]);
                    *reinterpret_cast<float2*>(out + r0 * OUT_F + n) = v0;
                    *reinterpret_cast<float2*>(out + (r0 + 8) * OUT_F + n) = v1;
                }
            }
        }

        t_cur = t_nxt;
        t_nxt = t_steal;
    }
}

// ---------------------------------------------------------------------------
// Launch: prep (resets counter) then persistent GEMM.
// ---------------------------------------------------------------------------
extern "C" void kernel_launch(void* const* d_in, const int* in_sizes, int n_in,
                              void* d_out, int out_size) {
    const float* x = (const float*)d_in[0];        // [4,2048,4096] fp32
    const int* indices = (const int*)d_in[1];      // [16777216] int32
    const int* q_scales = (const int*)d_in[2];     // [262144] int32
    float* out = (float*)d_out;                    // [4,2048,4096] fp32

    (void)in_sizes; (void)n_in; (void)out_size;

    prep_kernel<<<DQ_BLOCKS + CV_BLOCKS, 256>>>(indices, q_scales, x);

    cudaFuncSetAttribute(gemm_kernel,
                         cudaFuncAttributeMaxDynamicSharedMemorySize, SMEM_DYN);
    gemm_kernel<<<GRID_P, NTHREADS, SMEM_DYN>>>(out);
}